// round 13
// baseline (speedup 1.0000x reference)
#include <cuda_runtime.h>
#include <cstdint>

#define A_DIM 256
#define M_DIM 4
#define RBF   64
#define F_DIM 32
#define SI_N  32
#define H_DIM 32
#define BT    16
#define NTILES (A_DIM / BT)

// Effective fused radial weights: weff[tag][r][f] = sum_h w1[r,h]*w2[h,f]
__device__ float g_weff[4][RBF][F_DIM];
__device__ float g_beff[4][F_DIM];
// Pre-packed operands (TMA-friendly, compute-ready):
__device__ __align__(256) float4 g_vec4[M_DIM * A_DIM * A_DIM];   // masked (x,y,z,0)
__device__ __align__(256) float4 g_f1q[M_DIM * A_DIM * F_DIM];    // (fx,fy,fz,0)

// ---------------- PTX helpers ----------------
__device__ __forceinline__ uint32_t smem_u32(const void* p) {
    return (uint32_t)__cvta_generic_to_shared(p);
}
__device__ __forceinline__ void mbar_init(uint32_t mbar, uint32_t cnt) {
    asm volatile("mbarrier.init.shared.b64 [%0], %1;" :: "r"(mbar), "r"(cnt) : "memory");
}
__device__ __forceinline__ void mbar_expect_tx(uint32_t mbar, uint32_t bytes) {
    asm volatile("mbarrier.arrive.expect_tx.shared.b64 _, [%0], %1;"
                 :: "r"(mbar), "r"(bytes) : "memory");
}
__device__ __forceinline__ void mbar_wait(uint32_t mbar, uint32_t parity) {
    asm volatile(
        "{\n\t.reg .pred P;\n"
        "WL_%=:\n\t"
        "mbarrier.try_wait.parity.acquire.cta.shared::cta.b64 P, [%0], %1, 0x989680;\n\t"
        "@P bra WD_%=;\n\t"
        "bra WL_%=;\n"
        "WD_%=:\n\t}"
        :: "r"(mbar), "r"(parity) : "memory");
}
__device__ __forceinline__ void tma_bulk_g2s(uint32_t dst, const void* src,
                                             uint32_t bytes, uint32_t mbar) {
    asm volatile(
        "cp.async.bulk.shared::cluster.global.mbarrier::complete_tx::bytes "
        "[%0], [%1], %2, [%3];"
        :: "r"(dst), "l"(src), "r"(bytes), "r"(mbar) : "memory");
}

// ---------------- prep kernels ----------------
// grid (4, 8): blockIdx.x = tag, blockIdx.y = slice of the 2048 outputs
__global__ void prep_kernel(
    const float* __restrict__ w1_00, const float* __restrict__ b1_00,
    const float* __restrict__ w2_00, const float* __restrict__ b2_00,
    const float* __restrict__ w1_01, const float* __restrict__ b1_01,
    const float* __restrict__ w2_01, const float* __restrict__ b2_01,
    const float* __restrict__ w1_10, const float* __restrict__ b1_10,
    const float* __restrict__ w2_10, const float* __restrict__ b2_10,
    const float* __restrict__ w1_11, const float* __restrict__ b1_11,
    const float* __restrict__ w2_11, const float* __restrict__ b2_11)
{
    int tag = blockIdx.x;
    const float *w1, *b1, *w2, *b2;
    switch (tag) {
        case 0:  w1 = w1_00; b1 = b1_00; w2 = w2_00; b2 = b2_00; break;
        case 1:  w1 = w1_01; b1 = b1_01; w2 = w2_01; b2 = b2_01; break;
        case 2:  w1 = w1_10; b1 = b1_10; w2 = w2_10; b2 = b2_10; break;
        default: w1 = w1_11; b1 = b1_11; w2 = w2_11; b2 = b2_11; break;
    }
    int t = threadIdx.x;                          // 256 threads
    int idx = blockIdx.y * 256 + t;               // 0..2047 = r*32 + f
    int r = idx >> 5, f = idx & 31;
    float s = 0.f;
    #pragma unroll
    for (int h = 0; h < H_DIM; h++)
        s = fmaf(w1[r * H_DIM + h], w2[h * F_DIM + f], s);
    g_weff[tag][r][f] = s;
    if (blockIdx.y == 0 && t < F_DIM) {
        float b = b2[t];
        #pragma unroll
        for (int h = 0; h < H_DIM; h++)
            b = fmaf(b1[h], w2[h * F_DIM + t], b);
        g_beff[tag][t] = b;
    }
}

// Pack masked vectors -> float4, feat1 -> padded float4.
__global__ void prep_pack_kernel(const float* __restrict__ vectors,
                                 const float* __restrict__ feat1)
{
    int idx = blockIdx.x * 256 + threadIdx.x;           // 0 .. 262143
    const float* v = vectors + (size_t)idx * 3;
    float x = v[0], y = v[1], z = v[2];
    float n2 = x * x + y * y + z * z;
    bool masked = (n2 < 1e-14f);
    g_vec4[idx] = make_float4(masked ? 0.f : x, masked ? 0.f : y,
                              masked ? 0.f : z, 0.f);
    if (idx < M_DIM * A_DIM * F_DIM) {
        const float* f = feat1 + (size_t)idx * 3;
        g_f1q[idx] = make_float4(f[0], f[1], f[2], 0.f);
    }
}

// shifted softplus: log(0.5*exp(x)+0.5) = softplus(x) - ln2
__device__ __forceinline__ float ssp(float x) {
    return fmaxf(x, 0.f) + log1pf(expf(-fabsf(x))) - 0.69314718055994530942f;
}

#define TILE_BYTES (4096u + 2048u + 8192u + 256u)

__global__ __launch_bounds__(256, 3) void conv_kernel(
    const float* __restrict__ image,   // (M,A,A,RBF)
    const float* __restrict__ feat0,   // (M,A,F,1)
    const float* __restrict__ wsi0,    // (SI, 2F)
    const float* __restrict__ wsi1,    // (SI, 3F)
    const float* __restrict__ bact0,   // (SI,)
    const float* __restrict__ bact1,   // (SI,)
    float* __restrict__ out)           // o0 (M,A,SI,1) then o1 (M,A,SI,3)
{
    __shared__ __align__(16) float  simg[2][BT * 64];    // 2 x 4KB
    __shared__ __align__(16) float  sfeat0[2][BT * 32];  // 2 x 2KB
    __shared__ __align__(16) float4 sfeat1q[2][BT][32];  // 2 x 8KB
    __shared__ __align__(16) float4 svec[2][BT];         // 2 x 256B
    __shared__ __align__(8)  unsigned long long mbar[2];
    __shared__ float sepi[512];                          // half-merge scratch
    __shared__ float scat0[64];                          // cat0 channels
    __shared__ float scat1[96 * 3];                      // cat1 channels (ch*3+i)
    __shared__ float ssi1[96];                           // si1 pre-activation

    const int a   = blockIdx.x;
    const int m   = blockIdx.y;
    const int tid = threadIdx.x;
    const int sub  = tid & 127;     // (tag, f) pair id
    const int half = tid >> 7;      // which half of the r-dimension
    const int tag  = sub >> 5;      // 0:0x0  1:0x1  2:1x0  3:1x1
    const int f    = sub & 31;
    const int r0   = half << 5;

    const size_t rowIA = (size_t)(m * A_DIM + a) * A_DIM;   // (m,a,·) base
    const size_t rowMB = (size_t)m * A_DIM;                 // (m,·) base for feats

    const uint32_t mb[2] = { smem_u32(&mbar[0]), smem_u32(&mbar[1]) };

    if (tid == 0) { mbar_init(mb[0], 1); mbar_init(mb[1], 1); }
    __syncthreads();

    auto issue_tile = [&](int bt, int q) {
        const int b0 = bt * BT;
        mbar_expect_tx(mb[q], TILE_BYTES);
        tma_bulk_g2s(smem_u32(&simg[q][0]),    image + (rowIA + b0) * 64,        4096u, mb[q]);
        tma_bulk_g2s(smem_u32(&sfeat1q[q][0][0]), g_f1q + (rowMB + b0) * F_DIM,  8192u, mb[q]);
        tma_bulk_g2s(smem_u32(&sfeat0[q][0]),  feat0 + (rowMB + b0) * F_DIM,     2048u, mb[q]);
        tma_bulk_g2s(smem_u32(&svec[q][0]),    g_vec4 + rowIA + b0,              256u,  mb[q]);
    };

    if (tid == 0) issue_tile(0, 0);

    // Hoist this thread's effective weight column into registers (overlaps TMA).
    float W[32];
    #pragma unroll
    for (int k = 0; k < 32; k++) W[k] = g_weff[tag][r0 + k][f];
    const float bR = (half == 0) ? g_beff[tag][f] : 0.f;

    float acc0 = 0.f, acc1 = 0.f, acc2 = 0.f, acc3 = 0.f;
    int phase[2] = {0, 0};

    for (int bt = 0; bt < NTILES; bt++) {
        const int p = bt & 1;
        // Prefetch tile bt+1 into the other buffer (contents consumed by the
        // __syncthreads() that ended iteration bt-1).
        if (tid == 0 && bt + 1 < NTILES) issue_tile(bt + 1, 1 - p);

        mbar_wait(mb[p], phase[p]);
        phase[p] ^= 1;

        // ---- fused radial-GEMM + tensor-product accumulation ----
        const float* img_p = &simg[p][0];
        const float* f0_p  = &sfeat0[p][0];
        #pragma unroll 4
        for (int j = 0; j < BT; j++) {
            // 4 independent partial sums -> dependency chain 8 FMAs, not 32
            float R0 = bR, R1 = 0.f, R2 = 0.f, R3 = 0.f;
            const float4* ip = reinterpret_cast<const float4*>(img_p + j * 64 + r0);
            #pragma unroll
            for (int q = 0; q < 8; q++) {
                float4 v = ip[q];
                R0 = fmaf(v.x, W[4 * q + 0], R0);
                R1 = fmaf(v.y, W[4 * q + 1], R1);
                R2 = fmaf(v.z, W[4 * q + 2], R2);
                R3 = fmaf(v.w, W[4 * q + 3], R3);
            }
            float R = (R0 + R1) + (R2 + R3);

            if (tag == 0) {
                // out_0x0_0: scalar filter x feat0
                acc0 = fmaf(R, f0_p[j * 32 + f], acc0);
            } else if (tag == 1) {
                // out_0x1_1: (maskedvec * R) x feat0
                float4 v = svec[p][j];
                float t = R * f0_p[j * 32 + f];
                acc0 = fmaf(t, v.x, acc0);
                acc1 = fmaf(t, v.y, acc1);
                acc2 = fmaf(t, v.z, acc2);
            } else if (tag == 2) {
                // out_1x0_1: scalar filter x feat1
                float4 fv = sfeat1q[p][j][f];
                acc0 = fmaf(R, fv.x, acc0);
                acc1 = fmaf(R, fv.y, acc1);
                acc2 = fmaf(R, fv.z, acc2);
            } else {
                // out_1x1_0 (dot) and out_1x1_1 (cross); v already masked
                float4 v  = svec[p][j];
                float4 fv = sfeat1q[p][j][f];
                acc3 = fmaf(R, fmaf(v.x, fv.x, fmaf(v.y, fv.y, v.z * fv.z)), acc3);
                acc0 = fmaf(R, fmaf(v.y, fv.z, -v.z * fv.y), acc0);
                acc1 = fmaf(R, fmaf(v.z, fv.x, -v.x * fv.z), acc1);
                acc2 = fmaf(R, fmaf(v.x, fv.y, -v.y * fv.x), acc2);
            }
        }
        __syncthreads();   // buffer p fully consumed before iter bt+2 refills it
    }

    // ---- merge the two r-halves ----
    if (half == 1) {
        sepi[sub * 4 + 0] = acc0;
        sepi[sub * 4 + 1] = acc1;
        sepi[sub * 4 + 2] = acc2;
        sepi[sub * 4 + 3] = acc3;
    }
    __syncthreads();
    if (half == 0) {
        acc0 += sepi[sub * 4 + 0];
        acc1 += sepi[sub * 4 + 1];
        acc2 += sepi[sub * 4 + 2];
        acc3 += sepi[sub * 4 + 3];
        if (tag == 0) {
            scat0[f] = acc0;                             // cat0 ch f
        } else if (tag == 1) {
            scat1[3 * f + 0] = acc0;                     // cat1 ch f
            scat1[3 * f + 1] = acc1;
            scat1[3 * f + 2] = acc2;
        } else if (tag == 2) {
            scat1[3 * (32 + f) + 0] = acc0;              // cat1 ch 32+f
            scat1[3 * (32 + f) + 1] = acc1;
            scat1[3 * (32 + f) + 2] = acc2;
        } else {
            scat0[32 + f] = acc3;                        // cat0 ch 32+f
            scat1[3 * (64 + f) + 0] = acc0;              // cat1 ch 64+f
            scat1[3 * (64 + f) + 1] = acc1;
            scat1[3 * (64 + f) + 2] = acc2;
        }
    }
    __syncthreads();

    // ---- self-interaction + equivariant activation ----
    const int outbase = (m * A_DIM + a) * SI_N;
    if (tid < 32) {
        // scalar path: si0[g] -> shifted softplus
        float s = 0.f;
        #pragma unroll
        for (int ch = 0; ch < 64; ch++)
            s = fmaf(scat0[ch], wsi0[tid * 64 + ch], s);
        out[outbase + tid] = ssp(s + bact0[tid]);
    } else if (tid < 128) {
        int t2 = tid - 32;           // 0..95
        int g = t2 / 3, i = t2 % 3;
        float s = 0.f;
        #pragma unroll
        for (int ch = 0; ch < 96; ch++)
            s = fmaf(scat1[ch * 3 + i], wsi1[g * 96 + ch], s);
        ssi1[t2] = s;
    }
    __syncthreads();
    if (tid >= 32 && tid < 128) {
        int t2 = tid - 32;
        int g = t2 / 3, i = t2 % 3;
        float x = ssi1[g * 3 + 0], y = ssi1[g * 3 + 1], z = ssi1[g * 3 + 2];
        float n = sqrtf(fmaxf(x * x + y * y + z * z, 1e-7f));
        float scale = ssp(n + bact1[g]) / n;
        out[M_DIM * A_DIM * SI_N + (outbase + g) * 3 + i] = ssi1[t2] * scale;
    }
}

extern "C" void kernel_launch(void* const* d_in, const int* in_sizes, int n_in,
                              void* d_out, int out_size) {
    const float* image   = (const float*)d_in[0];
    const float* vectors = (const float*)d_in[1];
    const float* feat0   = (const float*)d_in[2];
    const float* feat1   = (const float*)d_in[3];
    // 4..19: w1/b1/w2/b2 for tags 00,01,10,11
    const float* wsi0  = (const float*)d_in[20];
    const float* wsi1  = (const float*)d_in[21];
    const float* bact0 = (const float*)d_in[22];
    const float* bact1 = (const float*)d_in[23];
    float* out = (float*)d_out;

    dim3 pgrid(4, 8);
    prep_kernel<<<pgrid, 256>>>(
        (const float*)d_in[4],  (const float*)d_in[5],  (const float*)d_in[6],  (const float*)d_in[7],
        (const float*)d_in[8],  (const float*)d_in[9],  (const float*)d_in[10], (const float*)d_in[11],
        (const float*)d_in[12], (const float*)d_in[13], (const float*)d_in[14], (const float*)d_in[15],
        (const float*)d_in[16], (const float*)d_in[17], (const float*)d_in[18], (const float*)d_in[19]);

    prep_pack_kernel<<<(M_DIM * A_DIM * A_DIM) / 256, 256>>>(vectors, feat1);

    dim3 grid(A_DIM, M_DIM);
    conv_kernel<<<grid, 256>>>(image, feat0, wsi0, wsi1, bact0, bact1, out);
}

// round 16
// speedup vs baseline: 1.6283x; 1.6283x over previous
#include <cuda_runtime.h>
#include <cstdint>

#define A_DIM 256
#define M_DIM 4
#define RBF   64
#define F_DIM 32
#define SI_N  32
#define H_DIM 32
#define BT    16
#define NTILES (A_DIM / BT)

// Effective fused radial weights: weff[tag][r][f] = sum_h w1[r,h]*w2[h,f]
__device__ float g_weff[4][RBF][F_DIM];
__device__ float g_beff[4][F_DIM];
// Pre-packed operands (TMA-friendly, compute-ready):
__device__ __align__(256) float4 g_vec4[M_DIM * A_DIM * A_DIM];   // masked (x,y,z,0)
__device__ __align__(256) float4 g_f1q[M_DIM * A_DIM * F_DIM];    // (fx,fy,fz,0)

// ---------------- PTX helpers ----------------
__device__ __forceinline__ uint32_t smem_u32(const void* p) {
    return (uint32_t)__cvta_generic_to_shared(p);
}
__device__ __forceinline__ void mbar_init(uint32_t mbar, uint32_t cnt) {
    asm volatile("mbarrier.init.shared.b64 [%0], %1;" :: "r"(mbar), "r"(cnt) : "memory");
}
__device__ __forceinline__ void mbar_expect_tx(uint32_t mbar, uint32_t bytes) {
    asm volatile("mbarrier.arrive.expect_tx.shared.b64 _, [%0], %1;"
                 :: "r"(mbar), "r"(bytes) : "memory");
}
__device__ __forceinline__ void mbar_wait(uint32_t mbar, uint32_t parity) {
    asm volatile(
        "{\n\t.reg .pred P;\n"
        "WL_%=:\n\t"
        "mbarrier.try_wait.parity.acquire.cta.shared::cta.b64 P, [%0], %1, 0x989680;\n\t"
        "@P bra WD_%=;\n\t"
        "bra WL_%=;\n"
        "WD_%=:\n\t}"
        :: "r"(mbar), "r"(parity) : "memory");
}
__device__ __forceinline__ void tma_bulk_g2s(uint32_t dst, const void* src,
                                             uint32_t bytes, uint32_t mbar) {
    asm volatile(
        "cp.async.bulk.shared::cluster.global.mbarrier::complete_tx::bytes "
        "[%0], [%1], %2, [%3];"
        :: "r"(dst), "l"(src), "r"(bytes), "r"(mbar) : "memory");
}

// ---------------- prep kernels ----------------
// grid (4, 8): blockIdx.x = tag, blockIdx.y = slice of the 2048 outputs
__global__ void prep_kernel(
    const float* __restrict__ w1_00, const float* __restrict__ b1_00,
    const float* __restrict__ w2_00, const float* __restrict__ b2_00,
    const float* __restrict__ w1_01, const float* __restrict__ b1_01,
    const float* __restrict__ w2_01, const float* __restrict__ b2_01,
    const float* __restrict__ w1_10, const float* __restrict__ b1_10,
    const float* __restrict__ w2_10, const float* __restrict__ b2_10,
    const float* __restrict__ w1_11, const float* __restrict__ b1_11,
    const float* __restrict__ w2_11, const float* __restrict__ b2_11)
{
    int tag = blockIdx.x;
    const float *w1, *b1, *w2, *b2;
    switch (tag) {
        case 0:  w1 = w1_00; b1 = b1_00; w2 = w2_00; b2 = b2_00; break;
        case 1:  w1 = w1_01; b1 = b1_01; w2 = w2_01; b2 = b2_01; break;
        case 2:  w1 = w1_10; b1 = b1_10; w2 = w2_10; b2 = b2_10; break;
        default: w1 = w1_11; b1 = b1_11; w2 = w2_11; b2 = b2_11; break;
    }
    int t = threadIdx.x;                          // 256 threads
    int idx = blockIdx.y * 256 + t;               // 0..2047 = r*32 + f
    int r = idx >> 5, f = idx & 31;
    float s = 0.f;
    #pragma unroll
    for (int h = 0; h < H_DIM; h++)
        s = fmaf(w1[r * H_DIM + h], w2[h * F_DIM + f], s);
    g_weff[tag][r][f] = s;
    if (blockIdx.y == 0 && t < F_DIM) {
        float b = b2[t];
        #pragma unroll
        for (int h = 0; h < H_DIM; h++)
            b = fmaf(b1[h], w2[h * F_DIM + t], b);
        g_beff[tag][t] = b;
    }
}

// Pack masked vectors -> float4, feat1 -> padded float4.
__global__ void prep_pack_kernel(const float* __restrict__ vectors,
                                 const float* __restrict__ feat1)
{
    int idx = blockIdx.x * 256 + threadIdx.x;           // 0 .. 262143
    const float* v = vectors + (size_t)idx * 3;
    float x = v[0], y = v[1], z = v[2];
    float n2 = x * x + y * y + z * z;
    bool masked = (n2 < 1e-14f);
    g_vec4[idx] = make_float4(masked ? 0.f : x, masked ? 0.f : y,
                              masked ? 0.f : z, 0.f);
    if (idx < M_DIM * A_DIM * F_DIM) {
        const float* f = feat1 + (size_t)idx * 3;
        g_f1q[idx] = make_float4(f[0], f[1], f[2], 0.f);
    }
}

// shifted softplus: log(0.5*exp(x)+0.5) = softplus(x) - ln2
__device__ __forceinline__ float ssp(float x) {
    return fmaxf(x, 0.f) + log1pf(expf(-fabsf(x))) - 0.69314718055994530942f;
}

#define TILE_BYTES (4096u + 2048u + 8192u + 256u)

__global__ __launch_bounds__(256, 3) void conv_kernel(
    const float* __restrict__ image,   // (M,A,A,RBF)
    const float* __restrict__ feat0,   // (M,A,F,1)
    const float* __restrict__ wsi0,    // (SI, 2F)
    const float* __restrict__ wsi1,    // (SI, 3F)
    const float* __restrict__ bact0,   // (SI,)
    const float* __restrict__ bact1,   // (SI,)
    float* __restrict__ out)           // o0 (M,A,SI,1) then o1 (M,A,SI,3)
{
    __shared__ __align__(16) float  simg[2][BT * 64];    // 2 x 4KB
    __shared__ __align__(16) float  sfeat0[2][BT * 32];  // 2 x 2KB
    __shared__ __align__(16) float4 sfeat1q[2][BT][32];  // 2 x 8KB
    __shared__ __align__(16) float4 svec[2][BT];         // 2 x 256B
    __shared__ __align__(8)  unsigned long long mbar[2];
    __shared__ float sepi[512];                          // half-merge scratch
    __shared__ float scat0[64];                          // cat0 channels
    __shared__ float scat1[96 * 3];                      // cat1 channels (ch*3+i)
    __shared__ float ssi1[96];                           // si1 pre-activation

    const int a   = blockIdx.x;
    const int m   = blockIdx.y;
    const int tid = threadIdx.x;
    const int sub  = tid & 127;     // (tag, f) pair id
    const int half = tid >> 7;      // which half of the r-dimension
    const int tag  = sub >> 5;      // 0:0x0  1:0x1  2:1x0  3:1x1
    const int f    = sub & 31;
    const int r0   = half << 5;

    const size_t rowIA = (size_t)(m * A_DIM + a) * A_DIM;   // (m,a,·) base
    const size_t rowMB = (size_t)m * A_DIM;                 // (m,·) base for feats

    const uint32_t mb[2] = { smem_u32(&mbar[0]), smem_u32(&mbar[1]) };

    if (tid == 0) { mbar_init(mb[0], 1); mbar_init(mb[1], 1); }
    __syncthreads();

    auto issue_tile = [&](int bt, int q) {
        const int b0 = bt * BT;
        mbar_expect_tx(mb[q], TILE_BYTES);
        tma_bulk_g2s(smem_u32(&simg[q][0]),    image + (rowIA + b0) * 64,        4096u, mb[q]);
        tma_bulk_g2s(smem_u32(&sfeat1q[q][0][0]), g_f1q + (rowMB + b0) * F_DIM,  8192u, mb[q]);
        tma_bulk_g2s(smem_u32(&sfeat0[q][0]),  feat0 + (rowMB + b0) * F_DIM,     2048u, mb[q]);
        tma_bulk_g2s(smem_u32(&svec[q][0]),    g_vec4 + rowIA + b0,              256u,  mb[q]);
    };

    if (tid == 0) issue_tile(0, 0);

    // Hoist this thread's effective weight column into registers (overlaps TMA).
    float W[32];
    #pragma unroll
    for (int k = 0; k < 32; k++) W[k] = g_weff[tag][r0 + k][f];
    const float bR = (half == 0) ? g_beff[tag][f] : 0.f;

    float acc0 = 0.f, acc1 = 0.f, acc2 = 0.f, acc3 = 0.f;
    int phase[2] = {0, 0};

    for (int bt = 0; bt < NTILES; bt++) {
        const int p = bt & 1;
        // Prefetch tile bt+1 into the other buffer (contents consumed by the
        // __syncthreads() that ended iteration bt-1).
        if (tid == 0 && bt + 1 < NTILES) issue_tile(bt + 1, 1 - p);

        mbar_wait(mb[p], phase[p]);
        phase[p] ^= 1;

        // ---- fused radial-GEMM + tensor-product accumulation ----
        const float* img_p = &simg[p][0];
        const float* f0_p  = &sfeat0[p][0];
        #pragma unroll 2
        for (int j = 0; j < BT; j++) {
            // 4 independent partial sums -> dependency chain 8 FMAs, not 32
            float R0 = bR, R1 = 0.f, R2 = 0.f, R3 = 0.f;
            const float4* ip = reinterpret_cast<const float4*>(img_p + j * 64 + r0);
            #pragma unroll
            for (int q = 0; q < 8; q++) {
                float4 v = ip[q];
                R0 = fmaf(v.x, W[4 * q + 0], R0);
                R1 = fmaf(v.y, W[4 * q + 1], R1);
                R2 = fmaf(v.z, W[4 * q + 2], R2);
                R3 = fmaf(v.w, W[4 * q + 3], R3);
            }
            float R = (R0 + R1) + (R2 + R3);

            if (tag == 0) {
                // out_0x0_0: scalar filter x feat0
                acc0 = fmaf(R, f0_p[j * 32 + f], acc0);
            } else if (tag == 1) {
                // out_0x1_1: (maskedvec * R) x feat0
                float4 v = svec[p][j];
                float t = R * f0_p[j * 32 + f];
                acc0 = fmaf(t, v.x, acc0);
                acc1 = fmaf(t, v.y, acc1);
                acc2 = fmaf(t, v.z, acc2);
            } else if (tag == 2) {
                // out_1x0_1: scalar filter x feat1
                float4 fv = sfeat1q[p][j][f];
                acc0 = fmaf(R, fv.x, acc0);
                acc1 = fmaf(R, fv.y, acc1);
                acc2 = fmaf(R, fv.z, acc2);
            } else {
                // out_1x1_0 (dot) and out_1x1_1 (cross); v already masked
                float4 v  = svec[p][j];
                float4 fv = sfeat1q[p][j][f];
                acc3 = fmaf(R, fmaf(v.x, fv.x, fmaf(v.y, fv.y, v.z * fv.z)), acc3);
                acc0 = fmaf(R, fmaf(v.y, fv.z, -v.z * fv.y), acc0);
                acc1 = fmaf(R, fmaf(v.z, fv.x, -v.x * fv.z), acc1);
                acc2 = fmaf(R, fmaf(v.x, fv.y, -v.y * fv.x), acc2);
            }
        }
        __syncthreads();   // buffer p fully consumed before iter bt+2 refills it
    }

    // ---- merge the two r-halves ----
    if (half == 1) {
        sepi[sub * 4 + 0] = acc0;
        sepi[sub * 4 + 1] = acc1;
        sepi[sub * 4 + 2] = acc2;
        sepi[sub * 4 + 3] = acc3;
    }
    __syncthreads();
    if (half == 0) {
        acc0 += sepi[sub * 4 + 0];
        acc1 += sepi[sub * 4 + 1];
        acc2 += sepi[sub * 4 + 2];
        acc3 += sepi[sub * 4 + 3];
        if (tag == 0) {
            scat0[f] = acc0;                             // cat0 ch f
        } else if (tag == 1) {
            scat1[3 * f + 0] = acc0;                     // cat1 ch f
            scat1[3 * f + 1] = acc1;
            scat1[3 * f + 2] = acc2;
        } else if (tag == 2) {
            scat1[3 * (32 + f) + 0] = acc0;              // cat1 ch 32+f
            scat1[3 * (32 + f) + 1] = acc1;
            scat1[3 * (32 + f) + 2] = acc2;
        } else {
            scat0[32 + f] = acc3;                        // cat0 ch 32+f
            scat1[3 * (64 + f) + 0] = acc0;              // cat1 ch 64+f
            scat1[3 * (64 + f) + 1] = acc1;
            scat1[3 * (64 + f) + 2] = acc2;
        }
    }
    __syncthreads();

    // ---- self-interaction + equivariant activation ----
    const int outbase = (m * A_DIM + a) * SI_N;
    if (tid < 32) {
        // scalar path: si0[g] -> shifted softplus
        float s = 0.f;
        #pragma unroll
        for (int ch = 0; ch < 64; ch++)
            s = fmaf(scat0[ch], wsi0[tid * 64 + ch], s);
        out[outbase + tid] = ssp(s + bact0[tid]);
    } else if (tid < 128) {
        int t2 = tid - 32;           // 0..95
        int g = t2 / 3, i = t2 % 3;
        float s = 0.f;
        #pragma unroll
        for (int ch = 0; ch < 96; ch++)
            s = fmaf(scat1[ch * 3 + i], wsi1[g * 96 + ch], s);
        ssi1[t2] = s;
    }
    __syncthreads();
    if (tid >= 32 && tid < 128) {
        int t2 = tid - 32;
        int g = t2 / 3, i = t2 % 3;
        float x = ssi1[g * 3 + 0], y = ssi1[g * 3 + 1], z = ssi1[g * 3 + 2];
        float n = sqrtf(fmaxf(x * x + y * y + z * z, 1e-7f));
        float scale = ssp(n + bact1[g]) / n;
        out[M_DIM * A_DIM * SI_N + (outbase + g) * 3 + i] = ssi1[t2] * scale;
    }
}

extern "C" void kernel_launch(void* const* d_in, const int* in_sizes, int n_in,
                              void* d_out, int out_size) {
    const float* image   = (const float*)d_in[0];
    const float* vectors = (const float*)d_in[1];
    const float* feat0   = (const float*)d_in[2];
    const float* feat1   = (const float*)d_in[3];
    // 4..19: w1/b1/w2/b2 for tags 00,01,10,11
    const float* wsi0  = (const float*)d_in[20];
    const float* wsi1  = (const float*)d_in[21];
    const float* bact0 = (const float*)d_in[22];
    const float* bact1 = (const float*)d_in[23];
    float* out = (float*)d_out;

    dim3 pgrid(4, 8);
    prep_kernel<<<pgrid, 256>>>(
        (const float*)d_in[4],  (const float*)d_in[5],  (const float*)d_in[6],  (const float*)d_in[7],
        (const float*)d_in[8],  (const float*)d_in[9],  (const float*)d_in[10], (const float*)d_in[11],
        (const float*)d_in[12], (const float*)d_in[13], (const float*)d_in[14], (const float*)d_in[15],
        (const float*)d_in[16], (const float*)d_in[17], (const float*)d_in[18], (const float*)d_in[19]);

    prep_pack_kernel<<<(M_DIM * A_DIM * A_DIM) / 256, 256>>>(vectors, feat1);

    dim3 grid(A_DIM, M_DIM);
    conv_kernel<<<grid, 256>>>(image, feat0, wsi0, wsi1, bact0, bact1, out);
}